// round 17
// baseline (speedup 1.0000x reference)
#include <cuda_runtime.h>
#include <cuda_bf16.h>
#include <math.h>
#include <stdint.h>

// ---------------- problem constants ----------------
#define BB        64
#define NN        128
#define FLAT      8192          // B*N
#define H_DIM     128
#define NODE_S    64
#define NODE_V    32
#define OUT_S     32
#define OUT_V     16
#define OUT_DIM   80
#define HIDN      128
#define NEE       512
#define EATT_N    4096
#define WN        4608
#define CUTOFF_F  5.0f
#define NORM_F    0.10206207261596575f   // 1/sqrt(96)
#define SQRT3_F   1.7320508075688772f
#define NACT_MAX  4096
#define ROWS3     32768         // B * NE
#define KWIN      64            // padded 49
#define KGIN      288           // padded 273

// ---------------- scratch (static device memory) ----------------
// g_winner holds edge+1 (0 = inactive). Statically zero-initialized; reset to 0
// at the END of each replay (tail of k_invs) so the graph is idempotent.
__device__ int   g_winner[FLAT];
__device__ int   g_active[FLAT];
__device__ int   g_posmap[FLAT];
__device__ int   g_count;
__device__ float g_ghid  [NACT_MAX * HIDN];
__device__ float g_env   [NACT_MAX];
__device__ float g_mul   [NACT_MAX];
__device__ float g_u     [NACT_MAX * 3];
__device__ float g_tpw   [NACT_MAX * WN];     // 75.5 MB
__device__ float g_vec   [NACT_MAX * OUT_DIM];
__device__ float g_vpart [BB * 4 * OUT_DIM];
__device__ float g_scales[NEE * 48];

// pre-split bf16 hi/lo packed operands (u32 = bf16x2 over consecutive k)
// activations: [row][K/2];  weights: [n][K/2] (transposed at split time)
__device__ __align__(16) unsigned g_winH[NACT_MAX * (KWIN/2)];
__device__ __align__(16) unsigned g_winL[NACT_MAX * (KWIN/2)];
__device__ __align__(16) unsigned g_ginH[NACT_MAX * (KGIN/2)];
__device__ __align__(16) unsigned g_ginL[NACT_MAX * (KGIN/2)];
__device__ __align__(16) unsigned g_hidH[NACT_MAX * (HIDN/2)];
__device__ __align__(16) unsigned g_hidL[NACT_MAX * (HIDN/2)];
__device__ __align__(16) unsigned g_invH[ROWS3 * 24];
__device__ __align__(16) unsigned g_invL[ROWS3 * 24];
__device__ __align__(16) unsigned g_x1H[ROWS3 * 64];
__device__ __align__(16) unsigned g_x1L[ROWS3 * 64];
__device__ __align__(16) unsigned g_x2H[ROWS3 * 64];
__device__ __align__(16) unsigned g_x2L[ROWS3 * 64];
__device__ __align__(16) unsigned g_wg1H[128 * 144];
__device__ __align__(16) unsigned g_wg1L[128 * 144];
__device__ __align__(16) unsigned g_w1H[128 * 32];
__device__ __align__(16) unsigned g_w1L[128 * 32];
__device__ __align__(16) unsigned g_w2H[4608 * 64];
__device__ __align__(16) unsigned g_w2L[4608 * 64];
__device__ __align__(16) unsigned g_wo1H[128 * 24];
__device__ __align__(16) unsigned g_wo1L[128 * 24];
__device__ __align__(16) unsigned g_wo2H[128 * 64];
__device__ __align__(16) unsigned g_wo2L[128 * 64];
__device__ __align__(16) unsigned g_wo3H[256 * 64];
__device__ __align__(16) unsigned g_wo3L[256 * 64];

__device__ __forceinline__ float siluf(float x) { return x / (1.0f + expf(-x)); }
__device__ __forceinline__ float sigmoidf_(float x) { return 1.0f / (1.0f + expf(-x)); }

__device__ __forceinline__ unsigned smem_u32(const void* p) {
    return (unsigned)__cvta_generic_to_shared(p);
}

// split a pair of fp32 into hi/lo bf16x2 packed words (low half = first elem)
__device__ __forceinline__ void split2(float x, float y, unsigned& hi, unsigned& lo) {
    __nv_bfloat162 hh = __floats2bfloat162_rn(x, y);
    float hx = __bfloat162float(__low2bfloat16(hh));
    float hy = __bfloat162float(__high2bfloat16(hh));
    __nv_bfloat162 ll = __floats2bfloat162_rn(x - hx, y - hy);
    hi = *reinterpret_cast<unsigned*>(&hh);
    lo = *reinterpret_cast<unsigned*>(&ll);
}

#define MMA_BF16(c, a, b)                                                        \
    asm volatile(                                                                \
        "mma.sync.aligned.m16n8k16.row.col.f32.bf16.bf16.f32 "                   \
        "{%0,%1,%2,%3},{%4,%5,%6,%7},{%8,%9},{%0,%1,%2,%3};"                     \
        : "+f"((c)[0]), "+f"((c)[1]), "+f"((c)[2]), "+f"((c)[3])                 \
        : "r"((a)[0]), "r"((a)[1]), "r"((a)[2]), "r"((a)[3]),                    \
          "r"((b)[0]), "r"((b)[1]))

#define LDSM4(R0, R1, R2, R3, ADDR)                                              \
    asm volatile(                                                                \
        "ldmatrix.sync.aligned.m8n8.x4.shared.b16 {%0,%1,%2,%3}, [%4];"          \
        : "=r"(R0), "=r"(R1), "=r"(R2), "=r"(R3) : "r"(ADDR))

__device__ __forceinline__ void cpa16(unsigned d, const void* s) {
    asm volatile("cp.async.cg.shared.global [%0], [%1], 16;" :: "r"(d), "l"(s));
}
#define CPA_COMMIT() asm volatile("cp.async.commit_group;" ::: "memory")
#define CPA_WAIT2()  asm volatile("cp.async.wait_group 2;" ::: "memory")

// ---------------- k_initw: edge scatter + weight pre-split (merged) ------------
#define SEG0 18432
#define SEG1 22528
#define SEG2 317440
#define SEG3 320512
#define SEG4 328704
#define SEG5 345088
__global__ void k_initw(const int* __restrict__ att_dst,
                        const float* __restrict__ wg1, const float* __restrict__ w1,
                        const float* __restrict__ w2,  const float* __restrict__ wo1,
                        const float* __restrict__ wo2, const float* __restrict__ wo3)
{
    int i = blockIdx.x * blockDim.x + threadIdx.x;
    if (i < EATT_N) atomicMax(&g_winner[att_dst[i]], i + 1);   // last-write-wins
    if (i >= SEG5) return;
    const float* src; unsigned *H, *L; int Nn, K2, Kreal, li;
    if (i < SEG0)      { src = wg1; H = g_wg1H; L = g_wg1L; Nn = 128;  K2 = 144; Kreal = 273; li = i; }
    else if (i < SEG1) { src = w1;  H = g_w1H;  L = g_w1L;  Nn = 128;  K2 = 32;  Kreal = 49;  li = i - SEG0; }
    else if (i < SEG2) { src = w2;  H = g_w2H;  L = g_w2L;  Nn = 4608; K2 = 64;  Kreal = 128; li = i - SEG1; }
    else if (i < SEG3) { src = wo1; H = g_wo1H; L = g_wo1L; Nn = 128;  K2 = 24;  Kreal = 48;  li = i - SEG2; }
    else if (i < SEG4) { src = wo2; H = g_wo2H; L = g_wo2L; Nn = 128;  K2 = 64;  Kreal = 128; li = i - SEG3; }
    else               { src = wo3; H = g_wo3H; L = g_wo3L; Nn = 256;  K2 = 64;  Kreal = 128; li = i - SEG4; }
    int n = li / K2, kp = li - n * K2;
    int k0 = 2 * kp;
    float x = (k0 < Kreal)     ? src[(size_t)k0 * Nn + n]       : 0.0f;
    float y = (k0 + 1 < Kreal) ? src[(size_t)(k0 + 1) * Nn + n] : 0.0f;
    unsigned hi, lo;
    split2(x, y, hi, lo);
    H[li] = hi; L[li] = lo;
}

__global__ void k_compact() {
    int i = blockIdx.x * blockDim.x + threadIdx.x;
    if (i < FLAT && g_winner[i] > 0) {
        int p = atomicAdd(&g_count, 1);
        g_active[p] = i;
        g_posmap[i] = p;
    }
}

// ---------------- k_prep: warp-per-pos input prep (+scales blocks) -------------
#define PREP_POS_BLOCKS (NACT_MAX / 4)
__global__ void __launch_bounds__(128)
k_prep(const float* __restrict__ h,
       const int*   __restrict__ z,
       const int*   __restrict__ absorber_index,
       const float* __restrict__ att_dist,
       const float* __restrict__ att_vec,
       const float* __restrict__ w_zemb,
       const float* __restrict__ e_feat,
       const float* __restrict__ we1, const float* __restrict__ be1,
       const float* __restrict__ we2, const float* __restrict__ be2)
{
    const int tid = threadIdx.x;
    if (blockIdx.x >= PREP_POS_BLOCKS) {
        // ---- scales MLP: one block per edge type ----
        __shared__ float hidd[HIDN];
        int e = blockIdx.x - PREP_POS_BLOCKS;
        float acc = be1[tid];
        for (int k = 0; k < 16; k++) acc += e_feat[e * 16 + k] * we1[k * HIDN + tid];
        hidd[tid] = siluf(acc);
        __syncthreads();
        if (tid < 48) {
            float s = be2[tid];
            for (int k = 0; k < HIDN; k++) s += hidd[k] * we2[k * 48 + tid];
            g_scales[e * 48 + tid] = s;
        }
        return;
    }
    const int warp = tid >> 5, lane = tid & 31;
    const int pos = blockIdx.x * 4 + warp;
    if (pos >= g_count) return;
    const int node = g_active[pos];
    const int b = node >> 7, n = node & 127;
    const int e = g_winner[node] - 1;
    const float d = att_dist[e];
    const int absb = absorber_index[b];
    const float isabs = (n == absb) ? 1.0f : 0.0f;
    const float width = CUTOFF_F / 15.0f;
    const float invwidth = 15.0f / CUTOFF_F;
    const int zn = z[node];
    unsigned hi, lo;

    // win row (64 padded, 49 used): [zemb 32 | isabs | rbf 16 | pad]
#pragma unroll
    for (int half = 0; half < 2; half++) {
        int j = half * 32 + lane;
        float v = 0.0f;
        if (j < 32)       v = w_zemb[zn * 32 + j];
        else if (j == 32) v = isabs;
        else if (j < 49) {
            float t = (d - (float)(j - 33) * width) * invwidth;
            v = expf(-0.5f * t * t);
        }
        float vp = __shfl_xor_sync(0xffffffffu, v, 1);
        if (!(lane & 1)) {
            split2(v, vp, hi, lo);
            g_winH[pos * 32 + (j >> 1)] = hi;
            g_winL[pos * 32 + (j >> 1)] = lo;
        }
    }
    // gin row: [h_abs 128 | h 128 | rbf16+isabs+pad 32]
    const float* habs = h + (size_t)(b * NN + absb) * H_DIM;
    const float* hown = h + (size_t)node * H_DIM;
#pragma unroll
    for (int c4 = 0; c4 < 4; c4++) {
        int j = c4 * 32 + lane;
        float v = habs[j];
        float vp = __shfl_xor_sync(0xffffffffu, v, 1);
        if (!(lane & 1)) {
            split2(v, vp, hi, lo);
            g_ginH[pos * 144 + (j >> 1)] = hi;
            g_ginL[pos * 144 + (j >> 1)] = lo;
        }
    }
#pragma unroll
    for (int c4 = 0; c4 < 4; c4++) {
        int j = c4 * 32 + lane;
        float v = hown[j];
        float vp = __shfl_xor_sync(0xffffffffu, v, 1);
        if (!(lane & 1)) {
            split2(v, vp, hi, lo);
            g_ginH[pos * 144 + 64 + (j >> 1)] = hi;
            g_ginL[pos * 144 + 64 + (j >> 1)] = lo;
        }
    }
    {
        float v = 0.0f;
        if (lane < 16) {
            float t = (d - (float)lane * width) * invwidth;
            v = expf(-0.5f * t * t);
        } else if (lane == 16) v = isabs;
        float vp = __shfl_xor_sync(0xffffffffu, v, 1);
        if (!(lane & 1)) {
            split2(v, vp, hi, lo);
            g_ginH[pos * 144 + 128 + (lane >> 1)] = hi;
            g_ginL[pos * 144 + 128 + (lane >> 1)] = lo;
        }
    }
    if (lane == 0)
        g_env[pos] = (d < CUTOFF_F) ? 0.5f * (cospif(d / CUTOFF_F) + 1.0f) : 0.0f;
    if (lane < 3)
        g_u[pos * 3 + lane] = att_vec[e * 3 + lane] / fmaxf(d, 1e-8f);
}

// ---------------- k_gate2 ----------------
__global__ void __launch_bounds__(256)
k_gate2(const float* __restrict__ wg2, const float* __restrict__ bg2)
{
    int wid = threadIdx.x >> 5, lane = threadIdx.x & 31;
    int pos = blockIdx.x * 8 + wid;
    if (pos >= g_count) return;
    float s = 0.0f;
#pragma unroll
    for (int j = 0; j < 4; j++) {
        int k = lane + 32 * j;
        s += g_ghid[pos * HIDN + k] * wg2[k];
    }
#pragma unroll
    for (int off = 16; off > 0; off >>= 1) s += __shfl_xor_sync(0xffffffffu, s, off);
    if (lane == 0)
        g_mul[pos] = sigmoidf_(s + bg2[0]) * g_env[pos] * NORM_F;
}

// ================= split-bf16 mma GEMM, 4-stage cp.async pipeline ==============
// C = act(A @ W + bias). Block tile 64x64, BK=16, 256 threads, 8 warps 4x2,
// warp tile 16x32 via m16n8k16. D = AhBh + AhBl + AlBh.
// A: [M][K/2] u32;  W: [n][K/2] u32 (weight pre-transposed at split).
// Rows stride 12 u32 (48B): conflict-free ldmatrix + cp.async stores.
// One commit-group per iteration (possibly empty); wait_group(2) => stage ready.
// 49152 B smem/CTA + 78 regs -> 3 CTAs/SM (24 warps, 50% occ).
// mode: 0 = f32 out, 1 = f32 + silu, 2 = split(hi/lo) + silu.
#define STG 4

struct GemmP {
    const unsigned *Ah, *Al, *Wh, *Wl;
    const float* bias;
    float* Cf; unsigned *CH, *CL;
    int N, K, mode;
};

__device__ __forceinline__ void bmma_body(const GemmP p, int bx, int by, char* smem)
{
    constexpr int AHSZ  = 64 * 12 * 4;      // 3072 bytes per tile (A or W, hi or lo)
    constexpr int AH_O  = 0;
    constexpr int AL_O  = AHSZ;
    constexpr int WH_O  = 2 * AHSZ;
    constexpr int WL_O  = 3 * AHSZ;
    constexpr int STGB  = 4 * AHSZ;         // 12288

    const unsigned sbase = smem_u32(smem);
    const int tid = threadIdx.x;
    const int wid = tid >> 5, lane = tid & 31;
    const int wm = wid & 3, wn = wid >> 2;
    const int g = lane >> 2, tig = lane & 3;
    const int m0 = by * 64, n0 = bx * 64;
    const int K2 = p.K >> 1;
    const int nk = p.K >> 4;

    const bool doA = (tid < 128);
    const int r2 = (tid & 127) >> 1, kp4 = (tid & 1) * 4;

    const int sel = lane >> 3;
    const int lrow = (lane & 7) + (sel & 1) * 8;
    const int lcol = (sel >> 1) * 4;
    const unsigned offA0 = ((wm * 16 + lrow) * 12 + lcol) * 4;
    const unsigned offB0 = ((wn * 32 + lrow) * 12 + lcol) * 4;
    const unsigned offB1 = ((wn * 32 + 16 + lrow) * 12 + lcol) * 4;

    const unsigned sdst = sbase + (r2 * 12 + kp4) * 4;
    const unsigned* srcH = doA ? (p.Ah + (size_t)(m0 + r2) * K2 + kp4)
                               : (p.Wh + (size_t)(n0 + r2) * K2 + kp4);
    const unsigned* srcL = doA ? (p.Al + (size_t)(m0 + r2) * K2 + kp4)
                               : (p.Wl + (size_t)(n0 + r2) * K2 + kp4);
    const unsigned oH = doA ? AH_O : WH_O;
    const unsigned oL = doA ? AL_O : WL_O;

    float cacc[4][4];
#pragma unroll
    for (int nt = 0; nt < 4; nt++)
#pragma unroll
        for (int i = 0; i < 4; i++) cacc[nt][i] = 0.0f;

    // prologue: issue stages 0..STG-2
#pragma unroll
    for (int s = 0; s < STG - 1; s++) {
        if (s < nk) {
            unsigned sb = s * STGB;
            cpa16(sdst + sb + oH, srcH + s * 8);
            cpa16(sdst + sb + oL, srcL + s * 8);
        }
        CPA_COMMIT();
    }

    for (int it = 0; it < nk; it++) {
        CPA_WAIT2();
        __syncthreads();
        const int buf = it & (STG - 1);
        const unsigned bb = sbase + buf * STGB;

        unsigned Ah[4], Al[4], Bh[4][2], Bl[4][2];
        LDSM4(Ah[0], Ah[1], Ah[2], Ah[3], bb + AH_O + offA0);
        LDSM4(Al[0], Al[1], Al[2], Al[3], bb + AL_O + offA0);
        LDSM4(Bh[0][0], Bh[1][0], Bh[0][1], Bh[1][1], bb + WH_O + offB0);
        LDSM4(Bh[2][0], Bh[3][0], Bh[2][1], Bh[3][1], bb + WH_O + offB1);
        LDSM4(Bl[0][0], Bl[1][0], Bl[0][1], Bl[1][1], bb + WL_O + offB0);
        LDSM4(Bl[2][0], Bl[3][0], Bl[2][1], Bl[3][1], bb + WL_O + offB1);

        int s = it + STG - 1;
        if (s < nk) {
            unsigned sb = (s & (STG - 1)) * STGB;
            cpa16(sdst + sb + oH, srcH + s * 8);
            cpa16(sdst + sb + oL, srcL + s * 8);
        }
        CPA_COMMIT();

#pragma unroll
        for (int nt = 0; nt < 4; nt++) {
            MMA_BF16(cacc[nt], Ah, Bh[nt]);
            MMA_BF16(cacc[nt], Ah, Bl[nt]);
            MMA_BF16(cacc[nt], Al, Bh[nt]);
        }
    }

    // ---- epilogue ----
    const int N2 = p.N >> 1;
    int row0 = m0 + wm * 16 + g;
#pragma unroll
    for (int nt = 0; nt < 4; nt++) {
        int col = n0 + wn * 32 + nt * 8 + 2 * tig;
        float b0 = p.bias[col], b1 = p.bias[col + 1];
        float v00 = cacc[nt][0] + b0;
        float v01 = cacc[nt][1] + b1;
        float v10 = cacc[nt][2] + b0;
        float v11 = cacc[nt][3] + b1;
        if (p.mode != 0) { v00 = siluf(v00); v01 = siluf(v01); v10 = siluf(v10); v11 = siluf(v11); }
        if (p.mode == 2) {
            unsigned hi, lo;
            split2(v00, v01, hi, lo);
            p.CH[(size_t)row0 * N2 + (col >> 1)] = hi;
            p.CL[(size_t)row0 * N2 + (col >> 1)] = lo;
            split2(v10, v11, hi, lo);
            p.CH[(size_t)(row0 + 8) * N2 + (col >> 1)] = hi;
            p.CL[(size_t)(row0 + 8) * N2 + (col >> 1)] = lo;
        } else {
            float2 r0 = {v00, v01};
            float2 r1 = {v10, v11};
            *reinterpret_cast<float2*>(p.Cf + (size_t)row0 * p.N + col) = r0;
            *reinterpret_cast<float2*>(p.Cf + (size_t)(row0 + 8) * p.N + col) = r1;
        }
    }
}

#define GSMEM1 (STG * 4 * 64 * 12 * 4)    // 49152

__global__ void __launch_bounds__(256, 3)
k_bmma(GemmP p)
{
    extern __shared__ char smem[];
    bmma_body(p, blockIdx.x, blockIdx.y, smem);
}

// dual GEMM: blocks with x < split run p0, others p1
__global__ void __launch_bounds__(256, 3)
k_bmma2(GemmP p0, GemmP p1, int split)
{
    extern __shared__ char smem[];
    if ((int)blockIdx.x < split) bmma_body(p0, blockIdx.x, blockIdx.y, smem);
    else                         bmma_body(p1, blockIdx.x - split, blockIdx.y, smem);
}

// ---------------- k_contract: tpw(4608) x node tensors -> vec[pos][80] ---------
__global__ void __launch_bounds__(128)
k_contract(const float* __restrict__ h_full)
{
    __shared__ float s1[NODE_S];
    __shared__ float v1s[NODE_V * 3];
    __shared__ float bvi[NODE_V];
    __shared__ float uu[3];

    const int pos = blockIdx.x;
    if (pos >= g_count) return;
    const int tid = threadIdx.x;
    const int node = g_active[pos];
    const float* hf = h_full + (size_t)node * 160;

    if (tid < NODE_S) s1[tid] = hf[tid];
    if (tid < NODE_V * 3) v1s[tid] = hf[NODE_S + tid];
    if (tid < 3) uu[tid] = g_u[pos * 3 + tid];
    __syncthreads();
    if (tid < NODE_V)
        bvi[tid] = v1s[3 * tid] * uu[0] + v1s[3 * tid + 1] * uu[1] + v1s[3 * tid + 2] * uu[2];
    __syncthreads();

    const float* tp = g_tpw + (size_t)pos * WN;
    const float mul = g_mul[pos];

    if (tid < OUT_S) {
        int o = tid;
        float acc = 0.0f;
#pragma unroll 8
        for (int i = 0; i < NODE_S; i++) acc += s1[i] * tp[i * OUT_S + o];
#pragma unroll 8
        for (int i = 0; i < NODE_V; i++) acc += bvi[i] * tp[2048 + i * OUT_S + o];
        g_vec[(size_t)pos * OUT_DIM + o] = acc * mul;
    }
    if (tid >= 64 && tid < 112) {
        int t = tid - 64;
        int o = t & 15, c = t >> 4;      // o<16, c<3
        float sc = 0.0f, sd = 0.0f;
#pragma unroll 8
        for (int i = 0; i < NODE_S; i++) sc += s1[i] * tp[3072 + i * OUT_V + o];
#pragma unroll 8
        for (int i = 0; i < NODE_V; i++) sd += v1s[3 * i + c] * tp[4096 + i * OUT_V + o];
        float yv = SQRT3_F * uu[c];
        g_vec[(size_t)pos * OUT_DIM + OUT_S + o * 3 + c] = (sc * yv + sd) * mul;
    }
}

// ---------------- k_vabs1: deterministic per-batch partial reduce ---------------
__global__ void k_vabs1() {
    int b = blockIdx.x, ch = blockIdx.y, t = threadIdx.x;
    if (t >= OUT_DIM) return;
    float acc = 0.0f;
    int nbase = b * NN + ch * 32;
    for (int n = 0; n < 32; n++) {
        int node = nbase + n;
        if (g_winner[node] > 0)
            acc += g_vec[(size_t)g_posmap[node] * OUT_DIM + t];
    }
    g_vpart[(b * 4 + ch) * OUT_DIM + t] = acc;
}

// ---------------- k_invs: invariants (split bf16) + end-of-replay reset --------
__device__ __forceinline__ float vabs_of(int b, int j) {
    float a = g_vpart[(b * 4 + 0) * OUT_DIM + j];
    a += g_vpart[(b * 4 + 1) * OUT_DIM + j];
    a += g_vpart[(b * 4 + 2) * OUT_DIM + j];
    a += g_vpart[(b * 4 + 3) * OUT_DIM + j];
    return a;
}

__global__ void __launch_bounds__(256)
k_invs()
{
    int t = blockIdx.x * blockDim.x + threadIdx.x;
    if (t < FLAT) g_winner[t] = 0;
    if (t == 0)   g_count = 0;
    if (t >= ROWS3 * 24) return;
    int row = t / 24, jp = t - row * 24;
    int b = row >> 9, e = row & 511;
    float vals[2];
#pragma unroll
    for (int jj = 0; jj < 2; jj++) {
        int j = 2 * jp + jj;
        float v;
        if (j < OUT_S) {
            v = vabs_of(b, j) * g_scales[e * 48 + j];
        } else {
            int o = j - OUT_S;
            float s = g_scales[e * 48 + OUT_S + o];
            float x0 = vabs_of(b, OUT_S + o * 3 + 0) * s;
            float x1 = vabs_of(b, OUT_S + o * 3 + 1) * s;
            float x2 = vabs_of(b, OUT_S + o * 3 + 2) * s;
            v = sqrtf(x0 * x0 + x1 * x1 + x2 * x2 + 1e-12f);
        }
        vals[jj] = v;
    }
    unsigned hi, lo;
    split2(vals[0], vals[1], hi, lo);
    g_invH[row * 24 + jp] = hi;
    g_invL[row * 24 + jp] = lo;
}

// ---------------- launch ----------------
extern "C" void kernel_launch(void* const* d_in, const int* in_sizes, int n_in,
                              void* d_out, int out_size)
{
    const float* h        = (const float*)d_in[0];
    const float* h_full   = (const float*)d_in[1];
    const int*   z        = (const int*)  d_in[2];
    const float* e_feat   = (const float*)d_in[4];
    const int*   abs_idx  = (const int*)  d_in[5];
    const int*   att_dst  = (const int*)  d_in[6];
    const float* att_dist = (const float*)d_in[7];
    const float* att_vec  = (const float*)d_in[8];
    const float* w_zemb   = (const float*)d_in[9];
    const float* w1_rad   = (const float*)d_in[10];
    const float* b1_rad   = (const float*)d_in[11];
    const float* w2_rad   = (const float*)d_in[12];
    const float* b2_rad   = (const float*)d_in[13];
    const float* wg1      = (const float*)d_in[14];
    const float* bg1      = (const float*)d_in[15];
    const float* wg2      = (const float*)d_in[16];
    const float* bg2      = (const float*)d_in[17];
    const float* we1      = (const float*)d_in[18];
    const float* be1      = (const float*)d_in[19];
    const float* we2      = (const float*)d_in[20];
    const float* be2      = (const float*)d_in[21];
    const float* wo1      = (const float*)d_in[22];
    const float* bo1      = (const float*)d_in[23];
    const float* wo2      = (const float*)d_in[24];
    const float* bo2      = (const float*)d_in[25];
    const float* wo3      = (const float*)d_in[26];
    const float* bo3      = (const float*)d_in[27];
    float* out = (float*)d_out;

    float *d_ghid, *d_tpw;
    unsigned *d_winH, *d_winL, *d_ginH, *d_ginL, *d_hidH, *d_hidL;
    unsigned *d_invH, *d_invL, *d_x1H, *d_x1L, *d_x2H, *d_x2L;
    unsigned *d_wg1H, *d_wg1L, *d_w1H, *d_w1L, *d_w2H, *d_w2L;
    unsigned *d_wo1H, *d_wo1L, *d_wo2H, *d_wo2L, *d_wo3H, *d_wo3L;
    cudaGetSymbolAddress((void**)&d_ghid, g_ghid);
    cudaGetSymbolAddress((void**)&d_tpw,  g_tpw);
    cudaGetSymbolAddress((void**)&d_winH, g_winH);
    cudaGetSymbolAddress((void**)&d_winL, g_winL);
    cudaGetSymbolAddress((void**)&d_ginH, g_ginH);
    cudaGetSymbolAddress((void**)&d_ginL, g_ginL);
    cudaGetSymbolAddress((void**)&d_hidH, g_hidH);
    cudaGetSymbolAddress((void**)&d_hidL, g_hidL);
    cudaGetSymbolAddress((void**)&d_invH, g_invH);
    cudaGetSymbolAddress((void**)&d_invL, g_invL);
    cudaGetSymbolAddress((void**)&d_x1H,  g_x1H);
    cudaGetSymbolAddress((void**)&d_x1L,  g_x1L);
    cudaGetSymbolAddress((void**)&d_x2H,  g_x2H);
    cudaGetSymbolAddress((void**)&d_x2L,  g_x2L);
    cudaGetSymbolAddress((void**)&d_wg1H, g_wg1H);
    cudaGetSymbolAddress((void**)&d_wg1L, g_wg1L);
    cudaGetSymbolAddress((void**)&d_w1H,  g_w1H);
    cudaGetSymbolAddress((void**)&d_w1L,  g_w1L);
    cudaGetSymbolAddress((void**)&d_w2H,  g_w2H);
    cudaGetSymbolAddress((void**)&d_w2L,  g_w2L);
    cudaGetSymbolAddress((void**)&d_wo1H, g_wo1H);
    cudaGetSymbolAddress((void**)&d_wo1L, g_wo1L);
    cudaGetSymbolAddress((void**)&d_wo2H, g_wo2H);
    cudaGetSymbolAddress((void**)&d_wo2L, g_wo2L);
    cudaGetSymbolAddress((void**)&d_wo3H, g_wo3H);
    cudaGetSymbolAddress((void**)&d_wo3L, g_wo3L);

    cudaFuncSetAttribute(k_bmma,  cudaFuncAttributeMaxDynamicSharedMemorySize, GSMEM1);
    cudaFuncSetAttribute(k_bmma2, cudaFuncAttributeMaxDynamicSharedMemorySize, GSMEM1);

    // 1: edge scatter + weight split
    k_initw<<<(SEG5 + 255) / 256, 256>>>(att_dst, wg1, w1_rad, w2_rad, wo1, wo2, wo3);
    // 2: compact active nodes
    k_compact<<<(FLAT + 255) / 256, 256>>>();
    // 3: per-node input prep (warp-per-pos) + scales MLP
    k_prep<<<PREP_POS_BLOCKS + NEE, 128>>>(h, z, abs_idx, att_dist, att_vec, w_zemb,
                                           e_feat, we1, be1, we2, be2);

    GemmP pg = {d_ginH, d_ginL, d_wg1H, d_wg1L, bg1, d_ghid, nullptr, nullptr, 128, KGIN, 1};
    GemmP pr = {d_winH, d_winL, d_w1H, d_w1L, b1_rad, nullptr, d_hidH, d_hidL, 128, KWIN, 2};
    // 4 (PROFILED): fused gate (4096x128,K=288) + rad (4096x128,K=64)
    k_bmma2<<<dim3(4, NACT_MAX / 64), 256, GSMEM1>>>(pg, pr, 2);
    // 5
    k_gate2<<<NACT_MAX / 8, 256>>>(wg2, bg2);
    // 6: tpw = hid @ w2 + b2: 4096 x 4608, K=128
    GemmP pt = {d_hidH, d_hidL, d_w2H, d_w2L, b2_rad, d_tpw, nullptr, nullptr, WN, HIDN, 0};
    k_bmma<<<dim3(WN / 64, NACT_MAX / 64), 256, GSMEM1>>>(pt);
    // 7-8
    k_contract<<<NACT_MAX, 128>>>(h_full);
    k_vabs1<<<dim3(BB, 4), 80>>>();
    // 9: invariants + end-of-replay reset
    k_invs<<<(ROWS3 * 24 + 255) / 256, 256>>>();
    // 10-12: tail MLP
    GemmP p1 = {d_invH, d_invL, d_wo1H, d_wo1L, bo1, nullptr, d_x1H, d_x1L, 128, 48, 2};
    k_bmma<<<dim3(2, ROWS3 / 64), 256, GSMEM1>>>(p1);
    GemmP p2 = {d_x1H, d_x1L, d_wo2H, d_wo2L, bo2, nullptr, d_x2H, d_x2L, 128, HIDN, 2};
    k_bmma<<<dim3(2, ROWS3 / 64), 256, GSMEM1>>>(p2);
    GemmP p3 = {d_x2H, d_x2L, d_wo3H, d_wo3L, bo3, out, nullptr, nullptr, 256, HIDN, 0};
    k_bmma<<<dim3(4, ROWS3 / 64), 256, GSMEM1>>>(p3);
}